// round 8
// baseline (speedup 1.0000x reference)
#include <cuda_runtime.h>
#include <math.h>

#define BN      32768      // B*N
#define NPTS    8192       // N
#define G8      4096       // k_proj groups (T=8)
#define G4      8192       // gather-kernel groups (T=4)
#define NT_P    448
#define NW_P    14
#define NT_G    768
#define NW_G    24
#define GRID    152

typedef unsigned long long u64t;

// Scratch (device globals: no allocation allowed)
__device__ float g_P0[BN * 64];
__device__ float g_P1[BN * 64];
__device__ float g_Px2[BN * 64];
__device__ float g_P2[BN * 64];
__device__ float g_z[BN * 64];
__device__ unsigned int g_ctr[4];   // 0:k_proj 1:k_z 2:k_r 3:k_out

__device__ __forceinline__ u64t pack2(float lo, float hi) {
    u64t r; asm("mov.b64 %0, {%1, %2};" : "=l"(r) : "f"(lo), "f"(hi)); return r;
}
__device__ __forceinline__ float2 unpack2(u64t v) {
    float2 r; asm("mov.b64 {%0, %1}, %2;" : "=f"(r.x), "=f"(r.y) : "l"(v)); return r;
}
// Packed fp32x2 FMA (sm_100+; PTX-only, ptxas never auto-fuses)
__device__ __forceinline__ void ffma2(u64t &d, u64t a, u64t b) {
    asm("fma.rn.f32x2 %0, %1, %2, %0;" : "+l"(d) : "l"(a), "l"(b));
}

__device__ __forceinline__ float lrelu(float v) { return fmaxf(v, 0.1f * v); }
__device__ __forceinline__ float sigmoidf_(float v) { return 1.0f / (1.0f + __expf(-v)); }

__device__ __forceinline__ int next_group(unsigned int* ctr, int lane) {
    int g = 0;
    if (lane == 0) g = (int)atomicAdd(ctr, 1u);
    return __shfl_sync(0xffffffffu, g, 0);
}

// Batched 64x64 matmul tail, T=4 points. yb: [t][c] duplicated pairs (u64).
__device__ __forceinline__ void mm64b4(const u64t* __restrict__ yb,
                                       const float* __restrict__ Wm,
                                       u64t* acc, int l) {
    const u64t* Wu = (const u64t*)Wm;
#pragma unroll 8
    for (int c2 = 0; c2 < 32; c2++) {
        const int c0 = 2 * c2;
        u64t w0 = Wu[c0 * 32 + l];
        u64t w1 = Wu[(c0 + 1) * 32 + l];
#pragma unroll
        for (int t = 0; t < 4; t++) {
            ulonglong2 y = *(const ulonglong2*)(yb + t * 64 + c0);
            ffma2(acc[t], y.x, w0);
            ffma2(acc[t], y.y, w1);
        }
    }
}

// ---------------------------------------------------------------------------
// Kernel 1: projections (T=8, 14 warps).
// ---------------------------------------------------------------------------
__global__ __launch_bounds__(NT_P, 1) void k_proj(const float* __restrict__ h,
                                                  const float* __restrict__ x,
                                                  const float* __restrict__ W1,
                                                  const float* __restrict__ b1) {
    extern __shared__ float sm[];
    float* Wa0 = sm;              // 128*64
    float* Wa1 = sm + 8192;
    float* Wx2 = sm + 16384;      // 64*64

    for (int i = threadIdx.x; i < 8192; i += NT_P) {
        Wa0[i] = W1[i];
        Wa1[i] = W1[8384 + i];
    }
    for (int i = threadIdx.x; i < 4096; i += NT_P)
        Wx2[i] = W1[20864 + i];
    if (blockIdx.x == 0 && threadIdx.x == 0) g_ctr[3] = GRID * NW_G;  // seed for k_out
    __syncthreads();

    const int w = threadIdx.x >> 5, l = threadIdx.x & 31;
    const int d0 = 2 * l, d1 = d0 + 1;
    u64t* actd = (u64t*)(sm + 20480 + w * 2048);   // [t][c] 8*128 u64
    const u64t* Wa0u = (const u64t*)Wa0;
    const u64t* Wa1u = (const u64t*)Wa1;
    const u64t* Wx2u = (const u64t*)Wx2;

    const u64t bb0 = pack2(b1[d0], b1[d1]);
    const u64t bb1 = pack2(b1[64 + d0], b1[64 + d1]);
    const u64t bb2 = pack2(b1[128 + d0], b1[128 + d1]);

    int g = blockIdx.x * NW_P + w;      // static first group, then steal
    while (g < G8) {
        const int base = g * 8;

        __syncwarp();
#pragma unroll
        for (int t = 0; t < 8; t++) {
            float2 hv = ((const float2*)h)[(size_t)(base + t) * 32 + l];
            float2 xv = ((const float2*)x)[(size_t)(base + t) * 32 + l];
            ulonglong2 hd; hd.x = pack2(hv.x, hv.x); hd.y = pack2(hv.y, hv.y);
            ulonglong2 xd; xd.x = pack2(xv.x, xv.x); xd.y = pack2(xv.y, xv.y);
            *(ulonglong2*)(actd + t * 128 + d0) = hd;
            *(ulonglong2*)(actd + t * 128 + 64 + d0) = xd;
        }
        __syncwarp();

        u64t a0[8], a1[8], a2[8];
#pragma unroll
        for (int t = 0; t < 8; t++) { a0[t] = bb0; a1[t] = bb1; a2[t] = bb2; }

#pragma unroll 2
        for (int c2 = 0; c2 < 32; c2++) {
            const int c0 = 2 * c2;
            u64t wh0a = Wa0u[c0 * 32 + l],        wh0b = Wa0u[(c0 + 1) * 32 + l];
            u64t wx0a = Wa0u[(64 + c0) * 32 + l], wx0b = Wa0u[(65 + c0) * 32 + l];
            u64t wh1a = Wa1u[c0 * 32 + l],        wh1b = Wa1u[(c0 + 1) * 32 + l];
            u64t wx1a = Wa1u[(64 + c0) * 32 + l], wx1b = Wa1u[(65 + c0) * 32 + l];
            u64t wx2a = Wx2u[c0 * 32 + l],        wx2b = Wx2u[(c0 + 1) * 32 + l];
#pragma unroll
            for (int t = 0; t < 8; t++) {
                ulonglong2 yh = *(const ulonglong2*)(actd + t * 128 + c0);
                ulonglong2 yx = *(const ulonglong2*)(actd + t * 128 + 64 + c0);
                ffma2(a0[t], yh.x, wh0a); ffma2(a0[t], yh.y, wh0b);
                ffma2(a0[t], yx.x, wx0a); ffma2(a0[t], yx.y, wx0b);
                ffma2(a1[t], yh.x, wh1a); ffma2(a1[t], yh.y, wh1b);
                ffma2(a1[t], yx.x, wx1a); ffma2(a1[t], yx.y, wx1b);
                ffma2(a2[t], yx.x, wx2a); ffma2(a2[t], yx.y, wx2b);
            }
        }
#pragma unroll
        for (int t = 0; t < 8; t++) {
            ((float2*)g_P0)[(size_t)(base + t) * 32 + l] = unpack2(a0[t]);
            ((float2*)g_P1)[(size_t)(base + t) * 32 + l] = unpack2(a1[t]);
            ((float2*)g_Px2)[(size_t)(base + t) * 32 + l] = unpack2(a2[t]);
        }
        g = next_group(&g_ctr[0], l);
    }
}

// ---------------------------------------------------------------------------
// Kernel 2: conv0 gather + tail -> z   (T=4, 24 warps)
// ---------------------------------------------------------------------------
__global__ __launch_bounds__(NT_G, 1) void k_z(const float* __restrict__ W1,
                                               const float* __restrict__ W2,
                                               const float* __restrict__ b2,
                                               const float* __restrict__ W3,
                                               const float* __restrict__ b3,
                                               const int* __restrict__ nidx,
                                               const float* __restrict__ ef) {
    extern __shared__ float sm[];
    float* W2s = sm;               // 4096
    float* W3s = sm + 4096;        // 4096

    for (int i = threadIdx.x; i < 4096; i += NT_G) {
        W2s[i] = W2[i];
        W3s[i] = W3[i];
    }
    if (blockIdx.x == 0 && threadIdx.x == 0) g_ctr[0] = GRID * NW_P;  // seed for k_proj
    __syncthreads();

    const int w = threadIdx.x >> 5, l = threadIdx.x & 31;
    const int d0 = 2 * l, d1 = d0 + 1;
    float* wbase = sm + 8192 + w * 1024;
    u64t* yb = (u64t*)wbase;           // 256 u64
    int*  idxs = (int*)(wbase + 512);  // 128 ints
    float* ew = wbase + 640;           // 384 floats

    const float* Wb = W1 + 8192;
    const u64t e0 = pack2(Wb[d0], Wb[d1]);
    const u64t e1 = pack2(Wb[64 + d0], Wb[64 + d1]);
    const u64t e2 = pack2(Wb[128 + d0], Wb[128 + d1]);
    const u64t bias2 = pack2(b2[d0], b2[d1]);
    const u64t bias3 = pack2(b3[d0], b3[d1]);

    int g = blockIdx.x * NW_G + w;
    while (g < G4) {
        const int base = g * 4;
        __syncwarp();
#pragma unroll
        for (int t = 0; t < 4; t++)
            idxs[t * 32 + l] = nidx[(size_t)(base + t) * 32 + l];
#pragma unroll
        for (int i = 0; i < 12; i++)
            ew[i * 32 + l] = ef[(size_t)base * 96 + i * 32 + l];
        __syncwarp();

        const size_t rowb = (size_t)(base & ~(NPTS - 1)) * 64;
        const char* Pb = (const char*)(g_P0 + rowb + d0);
        float ma[4], mb[4];
#pragma unroll
        for (int t = 0; t < 4; t++) {
            float am = -3e38f, bm = -3e38f;
            const int* idxt = idxs + t * 32;
            const float* ewt = ew + t * 96;
#pragma unroll 8
            for (int k = 0; k < 32; k++) {
                u64t q = *(const u64t*)(Pb + ((size_t)idxt[k] << 8));
                float f0 = ewt[3 * k], f1 = ewt[3 * k + 1], f2 = ewt[3 * k + 2];
                ffma2(q, pack2(f0, f0), e0);
                ffma2(q, pack2(f1, f1), e1);
                ffma2(q, pack2(f2, f2), e2);
                float2 v = unpack2(q);
                am = fmaxf(am, v.x); bm = fmaxf(bm, v.y);
            }
            ma[t] = am; mb[t] = bm;
        }

        u64t acc[4];
        __syncwarp();
#pragma unroll
        for (int t = 0; t < 4; t++) {
            float ya = lrelu(ma[t]), yc = lrelu(mb[t]);
            ulonglong2 v; v.x = pack2(ya, ya); v.y = pack2(yc, yc);
            *(ulonglong2*)(yb + t * 64 + d0) = v;
        }
        __syncwarp();
#pragma unroll
        for (int t = 0; t < 4; t++) acc[t] = bias2;
        mm64b4(yb, W2s, acc, l);
        __syncwarp();
#pragma unroll
        for (int t = 0; t < 4; t++) {
            float2 v = unpack2(acc[t]);
            v.x = lrelu(v.x); v.y = lrelu(v.y);
            ulonglong2 u; u.x = pack2(v.x, v.x); u.y = pack2(v.y, v.y);
            *(ulonglong2*)(yb + t * 64 + d0) = u;
        }
        __syncwarp();
#pragma unroll
        for (int t = 0; t < 4; t++) acc[t] = bias3;
        mm64b4(yb, W3s, acc, l);
#pragma unroll
        for (int t = 0; t < 4; t++) {
            float2 v = unpack2(acc[t]);
            float2 zf; zf.x = sigmoidf_(v.x); zf.y = sigmoidf_(v.y);
            ((float2*)g_z)[(size_t)(base + t) * 32 + l] = zf;
        }
        g = next_group(&g_ctr[1], l);
    }
}

// ---------------------------------------------------------------------------
// Kernel 3: conv1 gather + tail -> r -> rh -> P2   (T=4, 24 warps)
// ---------------------------------------------------------------------------
__global__ __launch_bounds__(NT_G, 1) void k_r(const float* __restrict__ h,
                                               const float* __restrict__ W1,
                                               const float* __restrict__ W2,
                                               const float* __restrict__ b2,
                                               const float* __restrict__ W3,
                                               const float* __restrict__ b3,
                                               const int* __restrict__ nidx,
                                               const float* __restrict__ ef) {
    extern __shared__ float sm[];
    float* W2s = sm;               // 4096
    float* W3s = sm + 4096;        // 4096
    float* W1ch = sm + 8192;       // W1[2][0:64,:]

    for (int i = threadIdx.x; i < 4096; i += NT_G) {
        W2s[i] = W2[4096 + i];
        W3s[i] = W3[4096 + i];
        W1ch[i] = W1[16768 + i];
    }
    if (blockIdx.x == 0 && threadIdx.x == 0) g_ctr[1] = GRID * NW_G;  // seed for k_z
    __syncthreads();

    const int w = threadIdx.x >> 5, l = threadIdx.x & 31;
    const int d0 = 2 * l, d1 = d0 + 1;
    float* wbase = sm + 12288 + w * 1024;
    u64t* yb = (u64t*)wbase;
    int*  idxs = (int*)(wbase + 512);
    float* ew = wbase + 640;

    const float* Wb = W1 + 16576;
    const u64t e0 = pack2(Wb[d0], Wb[d1]);
    const u64t e1 = pack2(Wb[64 + d0], Wb[64 + d1]);
    const u64t e2 = pack2(Wb[128 + d0], Wb[128 + d1]);
    const u64t bias2 = pack2(b2[64 + d0], b2[64 + d1]);
    const u64t bias3 = pack2(b3[64 + d0], b3[64 + d1]);

    int g = blockIdx.x * NW_G + w;
    while (g < G4) {
        const int base = g * 4;
        __syncwarp();
#pragma unroll
        for (int t = 0; t < 4; t++)
            idxs[t * 32 + l] = nidx[(size_t)(base + t) * 32 + l];
#pragma unroll
        for (int i = 0; i < 12; i++)
            ew[i * 32 + l] = ef[(size_t)base * 96 + i * 32 + l];
        __syncwarp();

        const size_t rowb = (size_t)(base & ~(NPTS - 1)) * 64;
        const char* Pb = (const char*)(g_P1 + rowb + d0);
        float ma[4], mb[4];
#pragma unroll
        for (int t = 0; t < 4; t++) {
            float am = -3e38f, bm = -3e38f;
            const int* idxt = idxs + t * 32;
            const float* ewt = ew + t * 96;
#pragma unroll 8
            for (int k = 0; k < 32; k++) {
                u64t q = *(const u64t*)(Pb + ((size_t)idxt[k] << 8));
                float f0 = ewt[3 * k], f1 = ewt[3 * k + 1], f2 = ewt[3 * k + 2];
                ffma2(q, pack2(f0, f0), e0);
                ffma2(q, pack2(f1, f1), e1);
                ffma2(q, pack2(f2, f2), e2);
                float2 v = unpack2(q);
                am = fmaxf(am, v.x); bm = fmaxf(bm, v.y);
            }
            ma[t] = am; mb[t] = bm;
        }

        u64t acc[4];
        __syncwarp();
#pragma unroll
        for (int t = 0; t < 4; t++) {
            float ya = lrelu(ma[t]), yc = lrelu(mb[t]);
            ulonglong2 v; v.x = pack2(ya, ya); v.y = pack2(yc, yc);
            *(ulonglong2*)(yb + t * 64 + d0) = v;
        }
        __syncwarp();
#pragma unroll
        for (int t = 0; t < 4; t++) acc[t] = bias2;
        mm64b4(yb, W2s, acc, l);
        __syncwarp();
#pragma unroll
        for (int t = 0; t < 4; t++) {
            float2 v = unpack2(acc[t]);
            v.x = lrelu(v.x); v.y = lrelu(v.y);
            ulonglong2 u; u.x = pack2(v.x, v.x); u.y = pack2(v.y, v.y);
            *(ulonglong2*)(yb + t * 64 + d0) = u;
        }
        __syncwarp();
#pragma unroll
        for (int t = 0; t < 4; t++) acc[t] = bias3;
        mm64b4(yb, W3s, acc, l);
        __syncwarp();
#pragma unroll
        for (int t = 0; t < 4; t++) {
            float2 v = unpack2(acc[t]);
            float2 hv = ((const float2*)h)[(size_t)(base + t) * 32 + l];
            float ra = sigmoidf_(v.x) * hv.x;
            float rb = sigmoidf_(v.y) * hv.y;
            ulonglong2 u; u.x = pack2(ra, ra); u.y = pack2(rb, rb);
            *(ulonglong2*)(yb + t * 64 + d0) = u;
        }
        __syncwarp();
#pragma unroll
        for (int t = 0; t < 4; t++) {
            float2 px = ((const float2*)g_Px2)[(size_t)(base + t) * 32 + l];
            acc[t] = pack2(px.x, px.y);
        }
        mm64b4(yb, W1ch, acc, l);
#pragma unroll
        for (int t = 0; t < 4; t++)
            ((float2*)g_P2)[(size_t)(base + t) * 32 + l] = unpack2(acc[t]);
        g = next_group(&g_ctr[2], l);
    }
}

// ---------------------------------------------------------------------------
// Kernel 4: conv2 gather + tail -> q, out = h + z*(q-h)   (T=4, 24 warps)
// ---------------------------------------------------------------------------
__global__ __launch_bounds__(NT_G, 1) void k_out(const float* __restrict__ h,
                                                 const float* __restrict__ W1,
                                                 const float* __restrict__ W2,
                                                 const float* __restrict__ b2,
                                                 const float* __restrict__ W3,
                                                 const float* __restrict__ b3,
                                                 const int* __restrict__ nidx,
                                                 const float* __restrict__ ef,
                                                 float* __restrict__ out) {
    extern __shared__ float sm[];
    float* W2s = sm;               // 4096
    float* W3s = sm + 4096;        // 4096

    for (int i = threadIdx.x; i < 4096; i += NT_G) {
        W2s[i] = W2[8192 + i];
        W3s[i] = W3[8192 + i];
    }
    if (blockIdx.x == 0 && threadIdx.x == 0) g_ctr[2] = GRID * NW_G;  // seed for k_r
    __syncthreads();

    const int w = threadIdx.x >> 5, l = threadIdx.x & 31;
    const int d0 = 2 * l, d1 = d0 + 1;
    float* wbase = sm + 8192 + w * 1024;
    u64t* yb = (u64t*)wbase;
    int*  idxs = (int*)(wbase + 512);
    float* ew = wbase + 640;

    const float* Wb = W1 + 24960;
    const u64t e0 = pack2(Wb[d0], Wb[d1]);
    const u64t e1 = pack2(Wb[64 + d0], Wb[64 + d1]);
    const u64t e2 = pack2(Wb[128 + d0], Wb[128 + d1]);
    const u64t bias2 = pack2(b2[128 + d0], b2[128 + d1]);
    const u64t bias3 = pack2(b3[128 + d0], b3[128 + d1]);

    int g = blockIdx.x * NW_G + w;
    while (g < G4) {
        const int base = g * 4;
        __syncwarp();
#pragma unroll
        for (int t = 0; t < 4; t++)
            idxs[t * 32 + l] = nidx[(size_t)(base + t) * 32 + l];
#pragma unroll
        for (int i = 0; i < 12; i++)
            ew[i * 32 + l] = ef[(size_t)base * 96 + i * 32 + l];
        __syncwarp();

        const size_t rowb = (size_t)(base & ~(NPTS - 1)) * 64;
        const char* Pb = (const char*)(g_P2 + rowb + d0);
        float ma[4], mb[4];
#pragma unroll
        for (int t = 0; t < 4; t++) {
            float am = -3e38f, bm = -3e38f;
            const int* idxt = idxs + t * 32;
            const float* ewt = ew + t * 96;
#pragma unroll 8
            for (int k = 0; k < 32; k++) {
                u64t q = *(const u64t*)(Pb + ((size_t)idxt[k] << 8));
                float f0 = ewt[3 * k], f1 = ewt[3 * k + 1], f2 = ewt[3 * k + 2];
                ffma2(q, pack2(f0, f0), e0);
                ffma2(q, pack2(f1, f1), e1);
                ffma2(q, pack2(f2, f2), e2);
                float2 v = unpack2(q);
                am = fmaxf(am, v.x); bm = fmaxf(bm, v.y);
            }
            ma[t] = am; mb[t] = bm;
        }

        u64t acc[4];
        __syncwarp();
#pragma unroll
        for (int t = 0; t < 4; t++) {
            float ya = lrelu(ma[t]), yc = lrelu(mb[t]);
            ulonglong2 v; v.x = pack2(ya, ya); v.y = pack2(yc, yc);
            *(ulonglong2*)(yb + t * 64 + d0) = v;
        }
        __syncwarp();
#pragma unroll
        for (int t = 0; t < 4; t++) acc[t] = bias2;
        mm64b4(yb, W2s, acc, l);
        __syncwarp();
#pragma unroll
        for (int t = 0; t < 4; t++) {
            float2 v = unpack2(acc[t]);
            v.x = lrelu(v.x); v.y = lrelu(v.y);
            ulonglong2 u; u.x = pack2(v.x, v.x); u.y = pack2(v.y, v.y);
            *(ulonglong2*)(yb + t * 64 + d0) = u;
        }
        __syncwarp();
#pragma unroll
        for (int t = 0; t < 4; t++) acc[t] = bias3;
        mm64b4(yb, W3s, acc, l);
#pragma unroll
        for (int t = 0; t < 4; t++) {
            float2 v = unpack2(acc[t]);
            float qa = tanhf(v.x), qb = tanhf(v.y);
            float2 zf = ((const float2*)g_z)[(size_t)(base + t) * 32 + l];
            float2 hv = ((const float2*)h)[(size_t)(base + t) * 32 + l];
            float2 o;
            o.x = hv.x + zf.x * (qa - hv.x);
            o.y = hv.y + zf.y * (qb - hv.y);
            ((float2*)out)[(size_t)(base + t) * 32 + l] = o;
        }
        g = next_group(&g_ctr[3], l);
    }
}

// ---------------------------------------------------------------------------
extern "C" void kernel_launch(void* const* d_in, const int* in_sizes, int n_in,
                              void* d_out, int out_size) {
    const float* h  = (const float*)d_in[0];
    const float* x  = (const float*)d_in[1];
    // d_in[2] = c (unused by reference)
    const float* W1 = (const float*)d_in[3];
    const float* b1 = (const float*)d_in[4];
    const float* W2 = (const float*)d_in[5];
    const float* b2 = (const float*)d_in[6];
    const float* W3 = (const float*)d_in[7];
    const float* b3 = (const float*)d_in[8];
    const int* nidx = (const int*)d_in[9];
    const float* ef = (const float*)d_in[10];
    float* out = (float*)d_out;

    const int SMEM_PROJ = (20480 + NW_P * 2048) * 4;   // 196608 B
    const int SMEM_Z    = (8192  + NW_G * 1024) * 4;   // 131072 B
    const int SMEM_R    = (12288 + NW_G * 1024) * 4;   // 147456 B
    const int SMEM_OUT  = (8192  + NW_G * 1024) * 4;   // 131072 B
    cudaFuncSetAttribute(k_proj, cudaFuncAttributeMaxDynamicSharedMemorySize, SMEM_PROJ);
    cudaFuncSetAttribute(k_z,    cudaFuncAttributeMaxDynamicSharedMemorySize, SMEM_Z);
    cudaFuncSetAttribute(k_r,    cudaFuncAttributeMaxDynamicSharedMemorySize, SMEM_R);
    cudaFuncSetAttribute(k_out,  cudaFuncAttributeMaxDynamicSharedMemorySize, SMEM_OUT);

    k_proj<<<GRID, NT_P, SMEM_PROJ>>>(h, x, W1, b1);
    k_z   <<<GRID, NT_G, SMEM_Z>>>(W1, W2, b2, W3, b3, nidx, ef);
    k_r   <<<GRID, NT_G, SMEM_R>>>(h, W1, W2, b2, W3, b3, nidx, ef);
    k_out <<<GRID, NT_G, SMEM_OUT>>>(h, W1, W2, b2, W3, b3, nidx, ef, out);
}

// round 10
// speedup vs baseline: 1.5735x; 1.5735x over previous
#include <cuda_runtime.h>
#include <math.h>

#define BN      32768      // B*N
#define NPTS    8192       // N
#define G8      4096       // groups of 8 points
#define NT_P    448
#define NW_P    14
#define NT_G    512
#define NW_G    16
#define GRID    152

typedef unsigned long long u64t;

// Scratch (device globals: no allocation allowed)
__device__ float g_P01[BN * 128];   // interleaved: row = [P0 pair | P1 pair] per channel pair
__device__ float g_Px2[BN * 64];
__device__ float g_P2[BN * 64];
__device__ float g_z[BN * 64];
__device__ unsigned int g_ctr[3];   // 0:k_proj 1:k_zr 2:k_out

__device__ __forceinline__ u64t pack2(float lo, float hi) {
    u64t r; asm("mov.b64 %0, {%1, %2};" : "=l"(r) : "f"(lo), "f"(hi)); return r;
}
__device__ __forceinline__ float2 unpack2(u64t v) {
    float2 r; asm("mov.b64 {%0, %1}, %2;" : "=f"(r.x), "=f"(r.y) : "l"(v)); return r;
}
// Packed fp32x2 FMA (sm_100+; PTX-only, ptxas never auto-fuses)
__device__ __forceinline__ void ffma2(u64t &d, u64t a, u64t b) {
    asm("fma.rn.f32x2 %0, %1, %2, %0;" : "+l"(d) : "l"(a), "l"(b));
}

__device__ __forceinline__ float lrelu(float v) { return fmaxf(v, 0.1f * v); }
__device__ __forceinline__ float sigmoidf_(float v) { return 1.0f / (1.0f + __expf(-v)); }

__device__ __forceinline__ int next_group(unsigned int* ctr, int lane) {
    int g = 0;
    if (lane == 0) g = (int)atomicAdd(ctr, 1u);
    return __shfl_sync(0xffffffffu, g, 0);
}

// Batched 64x64 matmul tail, T=8 points. yb: [t][c] duplicated pairs (u64).
__device__ __forceinline__ void mm64b8(const u64t* __restrict__ yb,
                                       const float* __restrict__ Wm,
                                       u64t* acc, int l) {
    const u64t* Wu = (const u64t*)Wm;
#pragma unroll 8
    for (int c2 = 0; c2 < 32; c2++) {
        const int c0 = 2 * c2;
        u64t w0 = Wu[c0 * 32 + l];
        u64t w1 = Wu[(c0 + 1) * 32 + l];
#pragma unroll
        for (int t = 0; t < 8; t++) {
            ulonglong2 y = *(const ulonglong2*)(yb + t * 64 + c0);
            ffma2(acc[t], y.x, w0);
            ffma2(acc[t], y.y, w1);
        }
    }
}

// ---------------------------------------------------------------------------
// Kernel 1: projections (T=8, 14 warps).
//   P01 = interleaved(hx@W1[0][:128]+b1[0], hx@W1[1][:128]+b1[1]),
//   Px2 = x@W1[2][64:128]+b1[2]
// ---------------------------------------------------------------------------
__global__ __launch_bounds__(NT_P, 1) void k_proj(const float* __restrict__ h,
                                                  const float* __restrict__ x,
                                                  const float* __restrict__ W1,
                                                  const float* __restrict__ b1) {
    extern __shared__ float sm[];
    float* Wa0 = sm;              // 128*64
    float* Wa1 = sm + 8192;
    float* Wx2 = sm + 16384;      // 64*64

    for (int i = threadIdx.x; i < 8192; i += NT_P) {
        Wa0[i] = W1[i];
        Wa1[i] = W1[8384 + i];
    }
    for (int i = threadIdx.x; i < 4096; i += NT_P)
        Wx2[i] = W1[20864 + i];
    if (blockIdx.x == 0 && threadIdx.x == 0) g_ctr[1] = GRID * NW_G;  // seed k_zr
    __syncthreads();

    const int w = threadIdx.x >> 5, l = threadIdx.x & 31;
    const int d0 = 2 * l, d1 = d0 + 1;
    u64t* actd = (u64t*)(sm + 20480 + w * 2048);   // [t][c] 8*128 u64
    const u64t* Wa0u = (const u64t*)Wa0;
    const u64t* Wa1u = (const u64t*)Wa1;
    const u64t* Wx2u = (const u64t*)Wx2;

    const u64t bb0 = pack2(b1[d0], b1[d1]);
    const u64t bb1 = pack2(b1[64 + d0], b1[64 + d1]);
    const u64t bb2 = pack2(b1[128 + d0], b1[128 + d1]);

    int g = blockIdx.x * NW_P + w;      // static first group, then steal
    while (g < G8) {
        const int base = g * 8;

        __syncwarp();
#pragma unroll
        for (int t = 0; t < 8; t++) {
            float2 hv = ((const float2*)h)[(size_t)(base + t) * 32 + l];
            float2 xv = ((const float2*)x)[(size_t)(base + t) * 32 + l];
            ulonglong2 hd; hd.x = pack2(hv.x, hv.x); hd.y = pack2(hv.y, hv.y);
            ulonglong2 xd; xd.x = pack2(xv.x, xv.x); xd.y = pack2(xv.y, xv.y);
            *(ulonglong2*)(actd + t * 128 + d0) = hd;
            *(ulonglong2*)(actd + t * 128 + 64 + d0) = xd;
        }
        __syncwarp();

        u64t a0[8], a1[8], a2[8];
#pragma unroll
        for (int t = 0; t < 8; t++) { a0[t] = bb0; a1[t] = bb1; a2[t] = bb2; }

#pragma unroll 2
        for (int c2 = 0; c2 < 32; c2++) {
            const int c0 = 2 * c2;
            u64t wh0a = Wa0u[c0 * 32 + l],        wh0b = Wa0u[(c0 + 1) * 32 + l];
            u64t wx0a = Wa0u[(64 + c0) * 32 + l], wx0b = Wa0u[(65 + c0) * 32 + l];
            u64t wh1a = Wa1u[c0 * 32 + l],        wh1b = Wa1u[(c0 + 1) * 32 + l];
            u64t wx1a = Wa1u[(64 + c0) * 32 + l], wx1b = Wa1u[(65 + c0) * 32 + l];
            u64t wx2a = Wx2u[c0 * 32 + l],        wx2b = Wx2u[(c0 + 1) * 32 + l];
#pragma unroll
            for (int t = 0; t < 8; t++) {
                ulonglong2 yh = *(const ulonglong2*)(actd + t * 128 + c0);
                ulonglong2 yx = *(const ulonglong2*)(actd + t * 128 + 64 + c0);
                ffma2(a0[t], yh.x, wh0a); ffma2(a0[t], yh.y, wh0b);
                ffma2(a0[t], yx.x, wx0a); ffma2(a0[t], yx.y, wx0b);
                ffma2(a1[t], yh.x, wh1a); ffma2(a1[t], yh.y, wh1b);
                ffma2(a1[t], yx.x, wx1a); ffma2(a1[t], yx.y, wx1b);
                ffma2(a2[t], yx.x, wx2a); ffma2(a2[t], yx.y, wx2b);
            }
        }
#pragma unroll
        for (int t = 0; t < 8; t++) {
            float2 v0 = unpack2(a0[t]), v1 = unpack2(a1[t]);
            ((float4*)g_P01)[(size_t)(base + t) * 32 + l] =
                make_float4(v0.x, v0.y, v1.x, v1.y);
            ((float2*)g_Px2)[(size_t)(base + t) * 32 + l] = unpack2(a2[t]);
        }
        g = next_group(&g_ctr[0], l);
    }
}

// ---------------------------------------------------------------------------
// Kernel 2: fused gather conv0+conv1 (T=8, 16 warps, single LDG.128 gather),
//           tails -> z (stored), r -> rh -> P2
// ---------------------------------------------------------------------------
__global__ __launch_bounds__(NT_G, 1) void k_zr(const float* __restrict__ h,
                                                const float* __restrict__ W1,
                                                const float* __restrict__ W2,
                                                const float* __restrict__ b2,
                                                const float* __restrict__ W3,
                                                const float* __restrict__ b3,
                                                const int* __restrict__ nidx,
                                                const float* __restrict__ ef) {
    extern __shared__ float sm[];
    float* W2_0 = sm;
    float* W3_0 = sm + 4096;
    float* W2_1 = sm + 8192;
    float* W3_1 = sm + 12288;
    float* W1ch = sm + 16384;       // W1[2][0:64,:]

    for (int i = threadIdx.x; i < 4096; i += NT_G) {
        W2_0[i] = W2[i];        W3_0[i] = W3[i];
        W2_1[i] = W2[4096 + i]; W3_1[i] = W3[4096 + i];
        W1ch[i] = W1[16768 + i];
    }
    if (blockIdx.x == 0 && threadIdx.x == 0) g_ctr[2] = GRID * NW_G;  // seed k_out
    __syncthreads();

    const int w = threadIdx.x >> 5, l = threadIdx.x & 31;
    const int d0 = 2 * l, d1 = d0 + 1;
    float* wbase = sm + 20480 + w * 2304;
    u64t*   yb   = (u64t*)wbase;              // 512 u64 = 4KB
    int*    idxs = (int*)(wbase + 1024);      // 256 ints = 1KB
    float4* ew4  = (float4*)(wbase + 1280);   // 256 float4 = 4KB

    const float* Wb0 = W1 + 8192;
    const float* Wb1 = W1 + 16576;
    const u64t e0c0 = pack2(Wb0[d0], Wb0[d1]);
    const u64t e1c0 = pack2(Wb0[64 + d0], Wb0[64 + d1]);
    const u64t e2c0 = pack2(Wb0[128 + d0], Wb0[128 + d1]);
    const u64t e0c1 = pack2(Wb1[d0], Wb1[d1]);
    const u64t e1c1 = pack2(Wb1[64 + d0], Wb1[64 + d1]);
    const u64t e2c1 = pack2(Wb1[128 + d0], Wb1[128 + d1]);
    const u64t bias20 = pack2(b2[d0], b2[d1]),           bias30 = pack2(b3[d0], b3[d1]);
    const u64t bias21 = pack2(b2[64 + d0], b2[64 + d1]), bias31 = pack2(b3[64 + d0], b3[64 + d1]);

    int g = blockIdx.x * NW_G + w;
    while (g < G8) {
        const int base = g * 8;
        __syncwarp();
#pragma unroll
        for (int t = 0; t < 8; t++)
            idxs[t * 32 + l] = nidx[(size_t)(base + t) * 32 + l];
#pragma unroll
        for (int t = 0; t < 8; t++) {
            const float* efp = ef + (size_t)(base + t) * 96 + 3 * l;
            ew4[t * 32 + l] = make_float4(efp[0], efp[1], efp[2], 0.f);
        }
        __syncwarp();

        // interleaved gather: one LDG.128 per neighbor = (P0 pair, P1 pair)
        const char* Pb = (const char*)g_P01
                       + ((size_t)(base & ~(NPTS - 1)) << 9)   // row*512B
                       + ((size_t)d0 << 3);                     // lane*16B
        float m0a[8], m0b[8], m1a[8], m1b[8];
#pragma unroll
        for (int t = 0; t < 8; t++) {
            float a0m = -3e38f, b0m = -3e38f, a1m = -3e38f, b1m = -3e38f;
            const int* idxt = idxs + t * 32;
            const float4* ewt = ew4 + t * 32;
#pragma unroll 8
            for (int k = 0; k < 32; k++) {
                ulonglong2 q = *(const ulonglong2*)(Pb + ((size_t)idxt[k] << 9));
                float4 f = ewt[k];
                u64t p0 = pack2(f.x, f.x), p1 = pack2(f.y, f.y), p2 = pack2(f.z, f.z);
                ffma2(q.x, p0, e0c0); ffma2(q.x, p1, e1c0); ffma2(q.x, p2, e2c0);
                ffma2(q.y, p0, e0c1); ffma2(q.y, p1, e1c1); ffma2(q.y, p2, e2c1);
                float2 v0 = unpack2(q.x), v1 = unpack2(q.y);
                a0m = fmaxf(a0m, v0.x); b0m = fmaxf(b0m, v0.y);
                a1m = fmaxf(a1m, v1.x); b1m = fmaxf(b1m, v1.y);
            }
            m0a[t] = a0m; m0b[t] = b0m; m1a[t] = a1m; m1b[t] = b1m;
        }

        u64t acc[8];
        // --- conv0 tail -> z ---
        __syncwarp();
#pragma unroll
        for (int t = 0; t < 8; t++) {
            float ya = lrelu(m0a[t]), yc = lrelu(m0b[t]);
            ulonglong2 v; v.x = pack2(ya, ya); v.y = pack2(yc, yc);
            *(ulonglong2*)(yb + t * 64 + d0) = v;
        }
        __syncwarp();
#pragma unroll
        for (int t = 0; t < 8; t++) acc[t] = bias20;
        mm64b8(yb, W2_0, acc, l);
        __syncwarp();
#pragma unroll
        for (int t = 0; t < 8; t++) {
            float2 v = unpack2(acc[t]);
            v.x = lrelu(v.x); v.y = lrelu(v.y);
            ulonglong2 u; u.x = pack2(v.x, v.x); u.y = pack2(v.y, v.y);
            *(ulonglong2*)(yb + t * 64 + d0) = u;
        }
        __syncwarp();
#pragma unroll
        for (int t = 0; t < 8; t++) acc[t] = bias30;
        mm64b8(yb, W3_0, acc, l);
#pragma unroll
        for (int t = 0; t < 8; t++) {
            float2 v = unpack2(acc[t]);
            float2 zf; zf.x = sigmoidf_(v.x); zf.y = sigmoidf_(v.y);
            ((float2*)g_z)[(size_t)(base + t) * 32 + l] = zf;
        }

        // --- conv1 tail -> r -> rh -> P2 ---
        __syncwarp();
#pragma unroll
        for (int t = 0; t < 8; t++) {
            float ya = lrelu(m1a[t]), yc = lrelu(m1b[t]);
            ulonglong2 v; v.x = pack2(ya, ya); v.y = pack2(yc, yc);
            *(ulonglong2*)(yb + t * 64 + d0) = v;
        }
        __syncwarp();
#pragma unroll
        for (int t = 0; t < 8; t++) acc[t] = bias21;
        mm64b8(yb, W2_1, acc, l);
        __syncwarp();
#pragma unroll
        for (int t = 0; t < 8; t++) {
            float2 v = unpack2(acc[t]);
            v.x = lrelu(v.x); v.y = lrelu(v.y);
            ulonglong2 u; u.x = pack2(v.x, v.x); u.y = pack2(v.y, v.y);
            *(ulonglong2*)(yb + t * 64 + d0) = u;
        }
        __syncwarp();
#pragma unroll
        for (int t = 0; t < 8; t++) acc[t] = bias31;
        mm64b8(yb, W3_1, acc, l);
        __syncwarp();
#pragma unroll
        for (int t = 0; t < 8; t++) {
            float2 v = unpack2(acc[t]);
            float2 hv = ((const float2*)h)[(size_t)(base + t) * 32 + l];
            float ra = sigmoidf_(v.x) * hv.x;
            float rb = sigmoidf_(v.y) * hv.y;
            ulonglong2 u; u.x = pack2(ra, ra); u.y = pack2(rb, rb);
            *(ulonglong2*)(yb + t * 64 + d0) = u;
        }
        __syncwarp();
#pragma unroll
        for (int t = 0; t < 8; t++) {
            float2 px = ((const float2*)g_Px2)[(size_t)(base + t) * 32 + l];
            acc[t] = pack2(px.x, px.y);
        }
        mm64b8(yb, W1ch, acc, l);
#pragma unroll
        for (int t = 0; t < 8; t++)
            ((float2*)g_P2)[(size_t)(base + t) * 32 + l] = unpack2(acc[t]);
        g = next_group(&g_ctr[1], l);
    }
}

// ---------------------------------------------------------------------------
// Kernel 3: conv2 gather (T=8, 16 warps) + tail -> q, out = h + z*(q-h)
// ---------------------------------------------------------------------------
__global__ __launch_bounds__(NT_G, 1) void k_out(const float* __restrict__ h,
                                                 const float* __restrict__ W1,
                                                 const float* __restrict__ W2,
                                                 const float* __restrict__ b2,
                                                 const float* __restrict__ W3,
                                                 const float* __restrict__ b3,
                                                 const int* __restrict__ nidx,
                                                 const float* __restrict__ ef,
                                                 float* __restrict__ out) {
    extern __shared__ float sm[];
    float* W2s = sm;               // 4096
    float* W3s = sm + 4096;        // 4096

    for (int i = threadIdx.x; i < 4096; i += NT_G) {
        W2s[i] = W2[8192 + i];
        W3s[i] = W3[8192 + i];
    }
    if (blockIdx.x == 0 && threadIdx.x == 0) g_ctr[0] = GRID * NW_P;  // seed k_proj (next replay)
    __syncthreads();

    const int w = threadIdx.x >> 5, l = threadIdx.x & 31;
    const int d0 = 2 * l, d1 = d0 + 1;
    float* wbase = sm + 8192 + w * 2304;
    u64t*   yb   = (u64t*)wbase;
    int*    idxs = (int*)(wbase + 1024);
    float4* ew4  = (float4*)(wbase + 1280);

    const float* Wb = W1 + 24960;
    const u64t e0 = pack2(Wb[d0], Wb[d1]);
    const u64t e1 = pack2(Wb[64 + d0], Wb[64 + d1]);
    const u64t e2 = pack2(Wb[128 + d0], Wb[128 + d1]);
    const u64t bias2 = pack2(b2[128 + d0], b2[128 + d1]);
    const u64t bias3 = pack2(b3[128 + d0], b3[128 + d1]);

    int g = blockIdx.x * NW_G + w;
    while (g < G8) {
        const int base = g * 8;
        __syncwarp();
#pragma unroll
        for (int t = 0; t < 8; t++)
            idxs[t * 32 + l] = nidx[(size_t)(base + t) * 32 + l];
#pragma unroll
        for (int t = 0; t < 8; t++) {
            const float* efp = ef + (size_t)(base + t) * 96 + 3 * l;
            ew4[t * 32 + l] = make_float4(efp[0], efp[1], efp[2], 0.f);
        }
        __syncwarp();

        const char* Pb = (const char*)g_P2
                       + ((size_t)(base & ~(NPTS - 1)) << 8)   // row*256B
                       + ((size_t)d0 << 2);                     // lane*8B
        float ma[8], mb[8];
#pragma unroll
        for (int t = 0; t < 8; t++) {
            float am = -3e38f, bm = -3e38f;
            const int* idxt = idxs + t * 32;
            const float4* ewt = ew4 + t * 32;
#pragma unroll 8
            for (int k = 0; k < 32; k++) {
                u64t q = *(const u64t*)(Pb + ((size_t)idxt[k] << 8));
                float4 f = ewt[k];
                ffma2(q, pack2(f.x, f.x), e0);
                ffma2(q, pack2(f.y, f.y), e1);
                ffma2(q, pack2(f.z, f.z), e2);
                float2 v = unpack2(q);
                am = fmaxf(am, v.x); bm = fmaxf(bm, v.y);
            }
            ma[t] = am; mb[t] = bm;
        }

        u64t acc[8];
        __syncwarp();
#pragma unroll
        for (int t = 0; t < 8; t++) {
            float ya = lrelu(ma[t]), yc = lrelu(mb[t]);
            ulonglong2 v; v.x = pack2(ya, ya); v.y = pack2(yc, yc);
            *(ulonglong2*)(yb + t * 64 + d0) = v;
        }
        __syncwarp();
#pragma unroll
        for (int t = 0; t < 8; t++) acc[t] = bias2;
        mm64b8(yb, W2s, acc, l);
        __syncwarp();
#pragma unroll
        for (int t = 0; t < 8; t++) {
            float2 v = unpack2(acc[t]);
            v.x = lrelu(v.x); v.y = lrelu(v.y);
            ulonglong2 u; u.x = pack2(v.x, v.x); u.y = pack2(v.y, v.y);
            *(ulonglong2*)(yb + t * 64 + d0) = u;
        }
        __syncwarp();
#pragma unroll
        for (int t = 0; t < 8; t++) acc[t] = bias3;
        mm64b8(yb, W3s, acc, l);
#pragma unroll
        for (int t = 0; t < 8; t++) {
            float2 v = unpack2(acc[t]);
            float qa = tanhf(v.x), qb = tanhf(v.y);
            float2 zf = ((const float2*)g_z)[(size_t)(base + t) * 32 + l];
            float2 hv = ((const float2*)h)[(size_t)(base + t) * 32 + l];
            float2 o;
            o.x = hv.x + zf.x * (qa - hv.x);
            o.y = hv.y + zf.y * (qb - hv.y);
            ((float2*)out)[(size_t)(base + t) * 32 + l] = o;
        }
        g = next_group(&g_ctr[2], l);
    }
}

// ---------------------------------------------------------------------------
extern "C" void kernel_launch(void* const* d_in, const int* in_sizes, int n_in,
                              void* d_out, int out_size) {
    const float* h  = (const float*)d_in[0];
    const float* x  = (const float*)d_in[1];
    // d_in[2] = c (unused by reference)
    const float* W1 = (const float*)d_in[3];
    const float* b1 = (const float*)d_in[4];
    const float* W2 = (const float*)d_in[5];
    const float* b2 = (const float*)d_in[6];
    const float* W3 = (const float*)d_in[7];
    const float* b3 = (const float*)d_in[8];
    const int* nidx = (const int*)d_in[9];
    const float* ef = (const float*)d_in[10];
    float* out = (float*)d_out;

    const int SMEM_PROJ = (20480 + NW_P * 2048) * 4;   // 196608 B
    const int SMEM_ZR   = (20480 + NW_G * 2304) * 4;   // 229376 B
    const int SMEM_OUT  = (8192  + NW_G * 2304) * 4;   // 180224 B
    cudaFuncSetAttribute(k_proj, cudaFuncAttributeMaxDynamicSharedMemorySize, SMEM_PROJ);
    cudaFuncSetAttribute(k_zr,   cudaFuncAttributeMaxDynamicSharedMemorySize, SMEM_ZR);
    cudaFuncSetAttribute(k_out,  cudaFuncAttributeMaxDynamicSharedMemorySize, SMEM_OUT);

    k_proj<<<GRID, NT_P, SMEM_PROJ>>>(h, x, W1, b1);
    k_zr  <<<GRID, NT_G, SMEM_ZR>>>(h, W1, W2, b2, W3, b3, nidx, ef);
    k_out <<<GRID, NT_G, SMEM_OUT>>>(h, W1, W2, b2, W3, b3, nidx, ef, out);
}